// round 16
// baseline (speedup 1.0000x reference)
#include <cuda_runtime.h>
#include <cuda_fp16.h>
#include <math.h>
#include <stdint.h>

// ---------------- problem constants ----------------
#define NN   200000
#define NI   64
#define NFD  128
#define NE   256
#define BB   16
#define KK   27
#define KDD  8
#define NDD  (NN / 8)        // 25000

#define STATS_BLOCKS 512
#define TILE_M 128
#define ROWU 9                // padded A row stride in 16B units (128B + 16B pad)
#define STAGE_BYTES (TILE_M * ROWU * 16)   // 18432
#define CONV_SMEM (2 * STAGE_BYTES)        // A only, 2 stages = 36864 B
#define NCTA 1563             // conv grid
#define DOWNCTA 196
#define NCHUNK 98             // 27 (conv1) + 54 (conv2) + 1 (idconv) + 16 (down)

// ---------------- scratch (device globals; no allocation allowed) ----------------
__device__ __half g_a  [(size_t)NN * NFD];   // fp16 activations (BN+SiLU output)
__device__ __half g_h  [(size_t)NN * NFD];   // conv1+film output (fp16)
__device__ __half g_h2 [(size_t)NN * NFD];   // conv2+idconv output (fp16)
__device__ __half g_xr [(size_t)NN * NI];    // fp16-rounded x (idconv input)
__device__ float  g_part[STATS_BLOCKS * 2 * NI];
__device__ float  g_cpart[(size_t)NCTA * 256];   // per-CTA conv1 stats partials
__device__ float  g_mv [2 * NFD];
__device__ float  g_tp [BB * 2 * NFD];
// +1024 uint2 (= 2 k-steps) overread pad for unconditional B prefetch
__device__ uint2  g_PB [(size_t)NCHUNK * 2048 + 1024];

// ---------------- helpers ----------------
__device__ __forceinline__ float silu_f(float x) { return x / (1.0f + expf(-x)); }

__device__ __forceinline__ uint32_t smem_u32(const void* p) {
    uint32_t a;
    asm("{ .reg .u64 t; cvta.to.shared.u64 t, %1; cvt.u32.u64 %0, t; }" : "=r"(a) : "l"(p));
    return a;
}

__device__ __forceinline__ void ldsm4(uint32_t* d, uint32_t addr) {
    asm volatile("ldmatrix.sync.aligned.m8n8.x4.shared.b16 {%0,%1,%2,%3}, [%4];"
                 : "=r"(d[0]), "=r"(d[1]), "=r"(d[2]), "=r"(d[3]) : "r"(addr));
}

__device__ __forceinline__ void mma_f16(float* c, const uint32_t* a, uint32_t b0, uint32_t b1) {
    asm volatile("mma.sync.aligned.m16n8k16.row.col.f32.f16.f16.f32 "
                 "{%0,%1,%2,%3}, {%4,%5,%6,%7}, {%8,%9}, {%0,%1,%2,%3};"
                 : "+f"(c[0]), "+f"(c[1]), "+f"(c[2]), "+f"(c[3])
                 : "r"(a[0]), "r"(a[1]), "r"(a[2]), "r"(a[3]), "r"(b0), "r"(b1));
}

// B load pinned in L1 (evict_last): B chunks are shared by all CTAs and hot
__device__ __forceinline__ uint4 ldg_el(const uint4* p) {
    uint4 v;
    asm volatile("ld.global.nc.L1::evict_last.v4.u32 {%0,%1,%2,%3}, [%4];"
                 : "=r"(v.x), "=r"(v.y), "=r"(v.z), "=r"(v.w) : "l"(p));
    return v;
}

// ---------------- fused prologue ----------------
// blocks [0,512): bn_stats<64> on x + fp16 rounding of x -> xr
// blocks [512,904): B fragment prep (98 chunks x 4 quarter-blocks)
// block 904: tproj
__global__ void prologue_kernel(const float* __restrict__ x,
                                const float* __restrict__ T, const float* __restrict__ Wt,
                                const float* __restrict__ bt,
                                const float* __restrict__ W1, const float* __restrict__ W2,
                                const float* __restrict__ Wid, const float* __restrict__ Wd,
                                float* __restrict__ part, float* __restrict__ tp,
                                uint2* __restrict__ PB, __half* __restrict__ xr) {
    const int blk = blockIdx.x;
    const int t = threadIdx.x;
    if (blk < 512) {
        // ---- bn_stats on x (C=64) + round x -> xr ----
        constexpr int C = NI, G = 256 / C;
        __shared__ float sh[512];
        int c = t % C, g = t / C;
        float s = 0.f, s2 = 0.f;
        for (int r = blk * G + g; r < NN; r += 512 * G) {
            float v = x[(size_t)r * C + c];
            xr[(size_t)r * C + c] = __float2half_rn(v);
            s += v; s2 += v * v;
        }
        sh[t] = s; sh[256 + t] = s2;
        __syncthreads();
        if (t < C) {
            float a = 0.f, b = 0.f;
            #pragma unroll
            for (int gg = 0; gg < G; ++gg) { a += sh[gg * C + t]; b += sh[256 + gg * C + t]; }
            part[blk * (2 * C) + t]     = a;
            part[blk * (2 * C) + C + t] = b;
        }
    } else if (blk < 904) {
        // ---- B fragment prep, layout [chunk][kt][warpN][half][lane][nth] ----
        int b = blk - 512;
        int chunk = b >> 2, q = b & 3;
        const float* W; int CI, k, cc;
        if (chunk < 27)       { W = W1;  CI = 64;  k = chunk; cc = 0; }
        else if (chunk < 81)  { int c2 = chunk - 27; W = W2; CI = 128; k = c2 >> 1; cc = (c2 & 1) * 64; }
        else if (chunk == 81) { W = Wid; CI = 64;  k = 0; cc = 0; }
        else                  { int cd = chunk - 82; W = Wd; CI = 128; k = cd >> 1; cc = (cd & 1) * 64; }
        #pragma unroll
        for (int e = 0; e < 2; ++e) {
            int f = q * 512 + t * 2 + e;
            int kt = f >> 9, warpN = (f >> 7) & 3, half = (f >> 6) & 1;
            int lane = (f >> 1) & 31, nth = f & 1;
            int n  = warpN * 32 + (half * 2 + nth) * 8 + (lane >> 2);
            int ci = cc + kt * 16 + 2 * (lane & 3);
            const float* src = W + ((size_t)k * CI + ci) * 128 + n;
            unsigned h0 = __half_as_ushort(__float2half_rn(src[0]));
            unsigned h1 = __half_as_ushort(__float2half_rn(src[128]));
            unsigned h2 = __half_as_ushort(__float2half_rn(src[8 * 128]));
            unsigned h3 = __half_as_ushort(__float2half_rn(src[9 * 128]));
            uint2 v;
            v.x = h0 | (h1 << 16);
            v.y = h2 | (h3 << 16);
            PB[(size_t)chunk * 2048 + f] = v;
        }
    } else {
        // ---- time projection ----
        __shared__ float ts[BB * NE];
        for (int l = t; l < BB * NE; l += 256) ts[l] = silu_f(T[l]);
        __syncthreads();
        float acc[BB];
        #pragma unroll
        for (int b = 0; b < BB; ++b) acc[b] = 0.f;
        for (int e = 0; e < NE; ++e) {
            float w = Wt[e * 256 + t];
            #pragma unroll
            for (int b = 0; b < BB; ++b) acc[b] = fmaf(ts[b * NE + e], w, acc[b]);
        }
        float bias = bt[t];
        #pragma unroll
        for (int b = 0; b < BB; ++b) tp[b * 256 + t] = acc[b] + bias;
    }
}

// ---------------- BN finalize (from stats blocks) ----------------
template<int C>
__global__ void bn_finalize_kernel(const float* __restrict__ part, int nblocks, float invn,
                                   const float* __restrict__ g, const float* __restrict__ be,
                                   float* __restrict__ mv) {
    constexpr int G = 512 / C;
    __shared__ float sh[1024];
    int t = threadIdx.x;
    int c = t % C, gg = t / C;
    float s = 0.f, s2 = 0.f;
    for (int b = gg; b < nblocks; b += G) {
        s  += part[b * 2 * C + c];
        s2 += part[b * 2 * C + C + c];
    }
    sh[t] = s; sh[512 + t] = s2;
    __syncthreads();
    if (t < C) {
        float a = 0.f, bsum = 0.f;
        #pragma unroll
        for (int q = 0; q < G; ++q) { a += sh[q * C + t]; bsum += sh[512 + q * C + t]; }
        float mean = a * invn;
        float var  = bsum * invn - mean * mean;
        float istd = rsqrtf(var + 1e-5f);
        float A = istd * g[t];
        mv[t]     = A;
        mv[C + t] = be[t] - mean * A;
    }
}

// ---------------- BN2 finalize from per-CTA conv1 partials ----------------
__global__ void bn_finalize_cpart_kernel(const float* __restrict__ cpart, float invn,
                                         const float* __restrict__ g, const float* __restrict__ be,
                                         float* __restrict__ mv) {
    __shared__ float sh[1024];
    __shared__ float tot[256];
    int t = threadIdx.x;             // 1024 threads
    int c = t & 255, gg = t >> 8;    // 4 groups
    float s = 0.f;
    for (int b = gg; b < NCTA; b += 4) s += cpart[(size_t)b * 256 + c];
    sh[t] = s;
    __syncthreads();
    if (t < 256) tot[t] = sh[t] + sh[256 + t] + sh[512 + t] + sh[768 + t];
    __syncthreads();
    if (t < 128) {
        float mean = tot[t] * invn;
        float var  = tot[128 + t] * invn - mean * mean;
        float istd = rsqrtf(var + 1e-5f);
        float A = istd * g[t];
        mv[t]       = A;
        mv[128 + t] = be[t] - mean * A;
    }
}

// ---------------- BN apply + SiLU (fp32 in) -> fp16 ----------------
template<int C>
__global__ void bn_apply_silu_kernel(const float4* __restrict__ X, const float* __restrict__ mv,
                                     uint4* __restrict__ Y, int n8) {
    int i = blockIdx.x * 256 + threadIdx.x;
    if (i >= n8) return;
    int f = (i & (C / 8 - 1)) * 8;
    float4 v0 = X[2 * i], v1 = X[2 * i + 1];
    union { uint4 u; __half2 h[4]; } o;
    o.h[0] = __floats2half2_rn(silu_f(fmaf(v0.x, mv[f + 0], mv[C + f + 0])),
                               silu_f(fmaf(v0.y, mv[f + 1], mv[C + f + 1])));
    o.h[1] = __floats2half2_rn(silu_f(fmaf(v0.z, mv[f + 2], mv[C + f + 2])),
                               silu_f(fmaf(v0.w, mv[f + 3], mv[C + f + 3])));
    o.h[2] = __floats2half2_rn(silu_f(fmaf(v1.x, mv[f + 4], mv[C + f + 4])),
                               silu_f(fmaf(v1.y, mv[f + 5], mv[C + f + 5])));
    o.h[3] = __floats2half2_rn(silu_f(fmaf(v1.z, mv[f + 6], mv[C + f + 6])),
                               silu_f(fmaf(v1.w, mv[f + 7], mv[C + f + 7])));
    Y[i] = o.u;
}

// ---------------- BN apply + SiLU (fp16 in, C=128) -> fp16 ----------------
__global__ void bn_apply_silu_h16_kernel(const uint4* __restrict__ X, const float* __restrict__ mv,
                                         uint4* __restrict__ Y, int n8) {
    int i = blockIdx.x * 256 + threadIdx.x;
    if (i >= n8) return;
    int f = (i & 15) * 8;
    union { uint4 u; __half2 h[4]; } in;
    in.u = X[i];
    union { uint4 u; __half2 h[4]; } o;
    #pragma unroll
    for (int q = 0; q < 4; ++q) {
        float2 v = __half22float2(in.h[q]);
        o.h[q] = __floats2half2_rn(
            silu_f(fmaf(v.x, mv[f + 2 * q + 0], mv[128 + f + 2 * q + 0])),
            silu_f(fmaf(v.y, mv[f + 2 * q + 1], mv[128 + f + 2 * q + 1])));
    }
    Y[i] = o.u;
}

// ---------------- fp16 mma.sync gather-GEMM, B direct from permuted gmem ----------------
// MODE: 0 = plain fp32 out, 1 = bias + FiLM fp16 out + per-CTA stats, 2 = bias+bias2 + idconv, fp16 out
template<int CIN, int MODE>
__global__ __launch_bounds__(256, 2)
void conv_mma_kernel(const __half* __restrict__ X, const int* __restrict__ nbr,
                     const uint4* __restrict__ PB, int chunk0,
                     const float* __restrict__ bias, const float* __restrict__ bias2,
                     const float* __restrict__ tp, const int* __restrict__ b_idx,
                     const __half* __restrict__ Xid, float* __restrict__ cpart,
                     void* __restrict__ outv, int M, int K) {
    extern __shared__ char sm[];
    const uint32_t smA = smem_u32(sm);            // A: 2 x 18432 B

    constexpr int CPK = CIN / 64;
    const int MAIN  = K * CPK;
    const int TOTAL = MAIN + ((MODE == 2) ? 1 : 0);

    const int t = threadIdx.x;
    const int lane = t & 31, w = t >> 5;
    const int warpM = w >> 2, warpN = w & 3;
    const int rowBase = blockIdx.x * TILE_M;

    // loader roles: 8 threads per row (16B each), 4 rows per thread (spaced 32)
    const int lr8 = t >> 3;          // base row 0..31
    const int lh8 = t & 7;           // 16B unit within row

    const int aRow = warpM * 64 + (lane & 15);
    const int aSeg = lane >> 4;

    float acc[4][4][4];
    #pragma unroll
    for (int i = 0; i < 4; ++i)
        #pragma unroll
        for (int j = 0; j < 4; ++j)
            #pragma unroll
            for (int q = 0; q < 4; ++q) acc[i][j][q] = 0.f;

    // A-side chunk decode
    struct AChunk { const __half* a; int aCIN; int cc; };
    auto decode = [&](int c) -> AChunk {
        AChunk ch;
        if (MODE != 2 || c < MAIN) {
            int k  = c / CPK;
            ch.cc = (c - k * CPK) * 64;
            ch.a = X; ch.aCIN = CIN;
        } else {
            ch.a = Xid; ch.aCIN = 64; ch.cc = 0;
        }
        return ch;
    };

    // neighbor indices for this thread's 4 rows of chunk c (prefetched)
    int idxv[4];
    auto ldIdx4 = [&](int c) {
        if (c >= TOTAL) return;
        bool ident = (MODE == 2) && (c >= MAIN);
        const int* nb = ident ? nullptr : (nbr + (size_t)(c / CPK) * M);
        #pragma unroll
        for (int i = 0; i < 4; ++i) {
            int row = rowBase + lr8 + 32 * i;
            idxv[i] = (row < M) ? (nb ? nb[row] : row) : -1;
        }
    };

    uint4 va[4];
    auto gatherA = [&](const AChunk& ch) {
        #pragma unroll
        for (int i = 0; i < 4; ++i) {
            int idx = idxv[i];
            if (idx >= 0)
                va[i] = *((const uint4*)(ch.a + (size_t)idx * ch.aCIN + ch.cc) + lh8);
            else
                va[i] = make_uint4(0, 0, 0, 0);
        }
    };
    auto stsA = [&](int bu) {
        char* base = sm + bu * STAGE_BYTES;
        #pragma unroll
        for (int i = 0; i < 4; ++i)
            *(uint4*)(base + (((lr8 + 32 * i) * ROWU) + lh8) * 16) = va[i];
    };

    // B fragment prefetch: running pointer, stride 256 uint4 per k-step.
    // Unconditional issue (PB has 2 k-steps of overread padding); L1 evict_last.
    uint4 blo[2], bhi[2];
    const uint4* pb = PB + (size_t)chunk0 * 1024 + warpN * 64 + lane;
    #define ISSUE_B(p) do { blo[p] = ldg_el(pb); bhi[p] = ldg_el(pb + 32); pb += 256; } while (0)

    ISSUE_B(0);
    ISSUE_B(1);

    // prologue A: idx + gather for chunk 0, prefetch idx for chunk 1
    ldIdx4(0);
    {
        AChunk c0 = decode(0);
        gatherA(c0);
        ldIdx4(1);
    }

    for (int c = 0; c < TOTAL; ++c) {
        const int bu = c & 1;
        stsA(bu);
        // issue next chunk's gather BEFORE the barrier (idx already prefetched),
        // then prefetch idx for the chunk after that
        if (c + 1 < TOTAL) {
            AChunk cn = decode(c + 1);
            gatherA(cn);
            ldIdx4(c + 2);
        }
        __syncthreads();

        const uint32_t abuf = smA + bu * STAGE_BYTES;
        #pragma unroll
        for (int kt = 0; kt < 4; ++kt) {
            const int p = kt & 1;
            uint4 lo = blo[p], hi = bhi[p];
            ISSUE_B(p);
            uint32_t a[4][4];
            #pragma unroll
            for (int mt = 0; mt < 4; ++mt)
                ldsm4(a[mt], abuf + ((aRow + mt * 16) * ROWU + 2 * kt + aSeg) * 16);
            #pragma unroll
            for (int mt = 0; mt < 4; ++mt) {
                mma_f16(acc[mt][0], a[mt], lo.x, lo.y);
                mma_f16(acc[mt][1], a[mt], lo.z, lo.w);
                mma_f16(acc[mt][2], a[mt], hi.x, hi.y);
                mma_f16(acc[mt][3], a[mt], hi.z, hi.w);
            }
        }
    }
    #undef ISSUE_B

    // ---- epilogue ----
    float ss[8], sq[8];
    if (MODE == 1) {
        #pragma unroll
        for (int q = 0; q < 8; ++q) { ss[q] = 0.f; sq[q] = 0.f; }
    }
    #pragma unroll
    for (int mt = 0; mt < 4; ++mt) {
        int row0 = rowBase + warpM * 64 + mt * 16 + (lane >> 2);
        #pragma unroll
        for (int hr = 0; hr < 2; ++hr) {
            int row = row0 + 8 * hr;
            if (row >= M) continue;
            const float* tpr = (MODE == 1) ? (tp + b_idx[row] * 256) : nullptr;
            #pragma unroll
            for (int nt = 0; nt < 4; ++nt) {
                int col = warpN * 32 + nt * 8 + 2 * (lane & 3);
                float v0 = acc[mt][nt][2 * hr + 0];
                float v1 = acc[mt][nt][2 * hr + 1];
                if (MODE == 1) {
                    v0 = (v0 + bias[col])     * (1.f + tpr[col])     + tpr[128 + col];
                    v1 = (v1 + bias[col + 1]) * (1.f + tpr[col + 1]) + tpr[129 + col];
                    ss[2 * nt]     += v0; sq[2 * nt]     += v0 * v0;
                    ss[2 * nt + 1] += v1; sq[2 * nt + 1] += v1 * v1;
                    __half* out = (__half*)outv;
                    *(__half2*)(out + (size_t)row * 128 + col) = __floats2half2_rn(v0, v1);
                } else if (MODE == 2) {
                    v0 += bias[col] + bias2[col];
                    v1 += bias[col + 1] + bias2[col + 1];
                    __half* out = (__half*)outv;
                    *(__half2*)(out + (size_t)row * 128 + col) = __floats2half2_rn(v0, v1);
                } else {
                    float* out = (float*)outv;
                    *(float2*)(out + (size_t)row * 128 + col) = make_float2(v0, v1);
                }
            }
        }
    }

    if (MODE == 1) {
        #pragma unroll
        for (int q = 0; q < 8; ++q) {
            #pragma unroll
            for (int off = 4; off <= 16; off <<= 1) {
                ss[q] += __shfl_xor_sync(0xffffffff, ss[q], off);
                sq[q] += __shfl_xor_sync(0xffffffff, sq[q], off);
            }
        }
        __syncthreads();
        float* sstat = (float*)sm;       // [2 warpM][256]
        if (lane < 4) {
            #pragma unroll
            for (int nt = 0; nt < 4; ++nt)
                #pragma unroll
                for (int p = 0; p < 2; ++p) {
                    int col = warpN * 32 + nt * 8 + 2 * lane + p;
                    sstat[warpM * 256 + col]       = ss[2 * nt + p];
                    sstat[warpM * 256 + 128 + col] = sq[2 * nt + p];
                }
        }
        __syncthreads();
        if (t < 256)
            cpart[(size_t)blockIdx.x * 256 + t] = sstat[t] + sstat[256 + t];
    }
}

// ---------------- launch ----------------
extern "C" void kernel_launch(void* const* d_in, const int* in_sizes, int n_in,
                              void* d_out, int out_size) {
    const float* x     = (const float*)d_in[0];
    const float* t     = (const float*)d_in[1];
    const int*   b_idx = (const int*)  d_in[2];
    const int*   nbr   = (const int*)  d_in[3];
    const int*   nbrd  = (const int*)  d_in[4];
    const float* g1    = (const float*)d_in[5];
    const float* be1   = (const float*)d_in[6];
    const float* W1    = (const float*)d_in[7];
    const float* b1    = (const float*)d_in[8];
    const float* Wt    = (const float*)d_in[9];
    const float* bt    = (const float*)d_in[10];
    const float* g2    = (const float*)d_in[11];
    const float* be2   = (const float*)d_in[12];
    const float* W2    = (const float*)d_in[13];
    const float* b2    = (const float*)d_in[14];
    const float* Wid   = (const float*)d_in[15];
    const float* bid   = (const float*)d_in[16];
    const float* Wd    = (const float*)d_in[17];
    float* out = (float*)d_out;

    __half *pa, *ph, *ph2, *pxr;
    float *ppart, *pcpart, *pmv, *ptp;
    uint2 *pPB;
    cudaGetSymbolAddress((void**)&pa,     g_a);
    cudaGetSymbolAddress((void**)&ph,     g_h);
    cudaGetSymbolAddress((void**)&ph2,    g_h2);
    cudaGetSymbolAddress((void**)&pxr,    g_xr);
    cudaGetSymbolAddress((void**)&ppart,  g_part);
    cudaGetSymbolAddress((void**)&pcpart, g_cpart);
    cudaGetSymbolAddress((void**)&pmv,    g_mv);
    cudaGetSymbolAddress((void**)&ptp,    g_tp);
    cudaGetSymbolAddress((void**)&pPB,    g_PB);

    cudaFuncSetAttribute(conv_mma_kernel<64, 1>,  cudaFuncAttributeMaxDynamicSharedMemorySize, CONV_SMEM);
    cudaFuncSetAttribute(conv_mma_kernel<128, 2>, cudaFuncAttributeMaxDynamicSharedMemorySize, CONV_SMEM);
    cudaFuncSetAttribute(conv_mma_kernel<128, 0>, cudaFuncAttributeMaxDynamicSharedMemorySize, CONV_SMEM);

    const float invn = 1.0f / (float)NN;

    // launch 0: fused prologue (stats1 + round x | B-frag prep | tproj)
    prologue_kernel<<<905, 256>>>(x, t, Wt, bt, W1, W2, Wid, Wd,
                                  ppart, ptp, pPB, pxr);
    // launch 1: BN1 finalize
    bn_finalize_kernel<NI><<<1, 512>>>(ppart, STATS_BLOCKS, invn, g1, be1, pmv);
    // launch 2: BN1 apply + SiLU -> a (fp16)
    {
        int n8 = NN * NI / 8;
        bn_apply_silu_kernel<NI><<<(n8 + 255) / 256, 256>>>((const float4*)x, pmv, (uint4*)pa, n8);
    }
    // launch 3 (ncu-profiled): conv1 (+bias +FiLM + stats) -> h (fp16)
    conv_mma_kernel<64, 1><<<NCTA, 256, CONV_SMEM>>>(
        pa, nbr, (const uint4*)pPB, 0, b1, nullptr, ptp, b_idx, nullptr, pcpart, ph, NN, KK);
    // launch 4: BN2 finalize from conv1 partials
    bn_finalize_cpart_kernel<<<1, 1024>>>(pcpart, invn, g2, be2, pmv);
    // launch 5: BN2 apply + SiLU (fp16 in) -> a (fp16)
    {
        int n8 = NN * NFD / 8;
        bn_apply_silu_h16_kernel<<<(n8 + 255) / 256, 256>>>((const uint4*)ph, pmv, (uint4*)pa, n8);
    }
    // launch 6: conv2 + fused idconv (+b2+bid) -> h2 (fp16)
    conv_mma_kernel<128, 2><<<NCTA, 256, CONV_SMEM>>>(
        pa, nbr, (const uint4*)pPB, 27, b2, bid, nullptr, nullptr, pxr, nullptr, ph2, NN, KK);
    // launch 7: strided down conv -> out (fp32)
    conv_mma_kernel<128, 0><<<DOWNCTA, 256, CONV_SMEM>>>(
        ph2, nbrd, (const uint4*)pPB, 82, nullptr, nullptr, nullptr, nullptr, nullptr, nullptr,
        out, NDD, KDD);

    (void)in_sizes; (void)n_in; (void)out_size;
}

// round 17
// speedup vs baseline: 1.1216x; 1.1216x over previous
#include <cuda_runtime.h>
#include <cuda_fp16.h>
#include <math.h>
#include <stdint.h>

// ---------------- problem constants ----------------
#define NN   200000
#define NI   64
#define NFD  128
#define NE   256
#define BB   16
#define KK   27
#define KDD  8
#define NDD  (NN / 8)        // 25000

#define STATS_BLOCKS 512
#define TILE_M 128
#define ROWU 9                // padded A row stride in 16B units (128B + 16B pad)
#define STAGE_BYTES (TILE_M * ROWU * 16)   // 18432
#define CONV_SMEM (2 * STAGE_BYTES)        // A only, 2 stages = 36864 B
#define NCTA 1563             // conv grid
#define DOWNCTA 196
#define NCHUNK 98             // 27 (conv1) + 54 (conv2) + 1 (idconv) + 16 (down)

// ---------------- scratch (device globals; no allocation allowed) ----------------
__device__ __half g_a  [(size_t)NN * NFD];   // fp16 activations (BN+SiLU output)
__device__ __half g_h  [(size_t)NN * NFD];   // conv1+film output (fp16)
__device__ __half g_h2 [(size_t)NN * NFD];   // conv2+idconv output (fp16)
__device__ __half g_xr [(size_t)NN * NI];    // fp16-rounded x (idconv input)
__device__ float  g_part[STATS_BLOCKS * 2 * NI];
__device__ float  g_cpart[(size_t)NCTA * 256];   // per-CTA conv1 stats partials
__device__ float  g_mv [2 * NFD];
__device__ float  g_tp [BB * 2 * NFD];
// +1024 uint2 (= 2 k-steps) overread pad for unconditional B prefetch
__device__ uint2  g_PB [(size_t)NCHUNK * 2048 + 1024];

// ---------------- helpers ----------------
__device__ __forceinline__ float silu_f(float x) { return x / (1.0f + expf(-x)); }

__device__ __forceinline__ uint32_t smem_u32(const void* p) {
    uint32_t a;
    asm("{ .reg .u64 t; cvta.to.shared.u64 t, %1; cvt.u32.u64 %0, t; }" : "=r"(a) : "l"(p));
    return a;
}

__device__ __forceinline__ void ldsm4(uint32_t* d, uint32_t addr) {
    asm volatile("ldmatrix.sync.aligned.m8n8.x4.shared.b16 {%0,%1,%2,%3}, [%4];"
                 : "=r"(d[0]), "=r"(d[1]), "=r"(d[2]), "=r"(d[3]) : "r"(addr));
}

__device__ __forceinline__ void mma_f16(float* c, const uint32_t* a, uint32_t b0, uint32_t b1) {
    asm volatile("mma.sync.aligned.m16n8k16.row.col.f32.f16.f16.f32 "
                 "{%0,%1,%2,%3}, {%4,%5,%6,%7}, {%8,%9}, {%0,%1,%2,%3};"
                 : "+f"(c[0]), "+f"(c[1]), "+f"(c[2]), "+f"(c[3])
                 : "r"(a[0]), "r"(a[1]), "r"(a[2]), "r"(a[3]), "r"(b0), "r"(b1));
}

// B load pinned in L1 (evict_last): B chunks are shared by all CTAs and hot
__device__ __forceinline__ uint4 ldg_el(const uint4* p) {
    uint4 v;
    asm volatile("ld.global.nc.L1::evict_last.v4.u32 {%0,%1,%2,%3}, [%4];"
                 : "=r"(v.x), "=r"(v.y), "=r"(v.z), "=r"(v.w) : "l"(p));
    return v;
}

// ---------------- fused prologue ----------------
// blocks [0,512): bn_stats<64> on x + fp16 rounding of x -> xr
// blocks [512,904): B fragment prep (98 chunks x 4 quarter-blocks)
// block 904: tproj
__global__ void prologue_kernel(const float* __restrict__ x,
                                const float* __restrict__ T, const float* __restrict__ Wt,
                                const float* __restrict__ bt,
                                const float* __restrict__ W1, const float* __restrict__ W2,
                                const float* __restrict__ Wid, const float* __restrict__ Wd,
                                float* __restrict__ part, float* __restrict__ tp,
                                uint2* __restrict__ PB, __half* __restrict__ xr) {
    const int blk = blockIdx.x;
    const int t = threadIdx.x;
    if (blk < 512) {
        // ---- bn_stats on x (C=64) + round x -> xr ----
        constexpr int C = NI, G = 256 / C;
        __shared__ float sh[512];
        int c = t % C, g = t / C;
        float s = 0.f, s2 = 0.f;
        for (int r = blk * G + g; r < NN; r += 512 * G) {
            float v = x[(size_t)r * C + c];
            xr[(size_t)r * C + c] = __float2half_rn(v);
            s += v; s2 += v * v;
        }
        sh[t] = s; sh[256 + t] = s2;
        __syncthreads();
        if (t < C) {
            float a = 0.f, b = 0.f;
            #pragma unroll
            for (int gg = 0; gg < G; ++gg) { a += sh[gg * C + t]; b += sh[256 + gg * C + t]; }
            part[blk * (2 * C) + t]     = a;
            part[blk * (2 * C) + C + t] = b;
        }
    } else if (blk < 904) {
        // ---- B fragment prep, layout [chunk][kt][warpN][half][lane][nth] ----
        int b = blk - 512;
        int chunk = b >> 2, q = b & 3;
        const float* W; int CI, k, cc;
        if (chunk < 27)       { W = W1;  CI = 64;  k = chunk; cc = 0; }
        else if (chunk < 81)  { int c2 = chunk - 27; W = W2; CI = 128; k = c2 >> 1; cc = (c2 & 1) * 64; }
        else if (chunk == 81) { W = Wid; CI = 64;  k = 0; cc = 0; }
        else                  { int cd = chunk - 82; W = Wd; CI = 128; k = cd >> 1; cc = (cd & 1) * 64; }
        #pragma unroll
        for (int e = 0; e < 2; ++e) {
            int f = q * 512 + t * 2 + e;
            int kt = f >> 9, warpN = (f >> 7) & 3, half = (f >> 6) & 1;
            int lane = (f >> 1) & 31, nth = f & 1;
            int n  = warpN * 32 + (half * 2 + nth) * 8 + (lane >> 2);
            int ci = cc + kt * 16 + 2 * (lane & 3);
            const float* src = W + ((size_t)k * CI + ci) * 128 + n;
            unsigned h0 = __half_as_ushort(__float2half_rn(src[0]));
            unsigned h1 = __half_as_ushort(__float2half_rn(src[128]));
            unsigned h2 = __half_as_ushort(__float2half_rn(src[8 * 128]));
            unsigned h3 = __half_as_ushort(__float2half_rn(src[9 * 128]));
            uint2 v;
            v.x = h0 | (h1 << 16);
            v.y = h2 | (h3 << 16);
            PB[(size_t)chunk * 2048 + f] = v;
        }
    } else {
        // ---- time projection ----
        __shared__ float ts[BB * NE];
        for (int l = t; l < BB * NE; l += 256) ts[l] = silu_f(T[l]);
        __syncthreads();
        float acc[BB];
        #pragma unroll
        for (int b = 0; b < BB; ++b) acc[b] = 0.f;
        for (int e = 0; e < NE; ++e) {
            float w = Wt[e * 256 + t];
            #pragma unroll
            for (int b = 0; b < BB; ++b) acc[b] = fmaf(ts[b * NE + e], w, acc[b]);
        }
        float bias = bt[t];
        #pragma unroll
        for (int b = 0; b < BB; ++b) tp[b * 256 + t] = acc[b] + bias;
    }
}

// ---------------- BN finalize (from stats blocks) ----------------
template<int C>
__global__ void bn_finalize_kernel(const float* __restrict__ part, int nblocks, float invn,
                                   const float* __restrict__ g, const float* __restrict__ be,
                                   float* __restrict__ mv) {
    constexpr int G = 512 / C;
    __shared__ float sh[1024];
    int t = threadIdx.x;
    int c = t % C, gg = t / C;
    float s = 0.f, s2 = 0.f;
    for (int b = gg; b < nblocks; b += G) {
        s  += part[b * 2 * C + c];
        s2 += part[b * 2 * C + C + c];
    }
    sh[t] = s; sh[512 + t] = s2;
    __syncthreads();
    if (t < C) {
        float a = 0.f, bsum = 0.f;
        #pragma unroll
        for (int q = 0; q < G; ++q) { a += sh[q * C + t]; bsum += sh[512 + q * C + t]; }
        float mean = a * invn;
        float var  = bsum * invn - mean * mean;
        float istd = rsqrtf(var + 1e-5f);
        float A = istd * g[t];
        mv[t]     = A;
        mv[C + t] = be[t] - mean * A;
    }
}

// ---------------- BN2 finalize from per-CTA conv1 partials ----------------
__global__ void bn_finalize_cpart_kernel(const float* __restrict__ cpart, float invn,
                                         const float* __restrict__ g, const float* __restrict__ be,
                                         float* __restrict__ mv) {
    __shared__ float sh[1024];
    __shared__ float tot[256];
    int t = threadIdx.x;             // 1024 threads
    int c = t & 255, gg = t >> 8;    // 4 groups
    float s = 0.f;
    for (int b = gg; b < NCTA; b += 4) s += cpart[(size_t)b * 256 + c];
    sh[t] = s;
    __syncthreads();
    if (t < 256) tot[t] = sh[t] + sh[256 + t] + sh[512 + t] + sh[768 + t];
    __syncthreads();
    if (t < 128) {
        float mean = tot[t] * invn;
        float var  = tot[128 + t] * invn - mean * mean;
        float istd = rsqrtf(var + 1e-5f);
        float A = istd * g[t];
        mv[t]       = A;
        mv[128 + t] = be[t] - mean * A;
    }
}

// ---------------- BN apply + SiLU (fp32 in) -> fp16 ----------------
template<int C>
__global__ void bn_apply_silu_kernel(const float4* __restrict__ X, const float* __restrict__ mv,
                                     uint4* __restrict__ Y, int n8) {
    int i = blockIdx.x * 256 + threadIdx.x;
    if (i >= n8) return;
    int f = (i & (C / 8 - 1)) * 8;
    float4 v0 = X[2 * i], v1 = X[2 * i + 1];
    union { uint4 u; __half2 h[4]; } o;
    o.h[0] = __floats2half2_rn(silu_f(fmaf(v0.x, mv[f + 0], mv[C + f + 0])),
                               silu_f(fmaf(v0.y, mv[f + 1], mv[C + f + 1])));
    o.h[1] = __floats2half2_rn(silu_f(fmaf(v0.z, mv[f + 2], mv[C + f + 2])),
                               silu_f(fmaf(v0.w, mv[f + 3], mv[C + f + 3])));
    o.h[2] = __floats2half2_rn(silu_f(fmaf(v1.x, mv[f + 4], mv[C + f + 4])),
                               silu_f(fmaf(v1.y, mv[f + 5], mv[C + f + 5])));
    o.h[3] = __floats2half2_rn(silu_f(fmaf(v1.z, mv[f + 6], mv[C + f + 6])),
                               silu_f(fmaf(v1.w, mv[f + 7], mv[C + f + 7])));
    Y[i] = o.u;
}

// ---------------- BN apply + SiLU (fp16 in, C=128) -> fp16 ----------------
__global__ void bn_apply_silu_h16_kernel(const uint4* __restrict__ X, const float* __restrict__ mv,
                                         uint4* __restrict__ Y, int n8) {
    int i = blockIdx.x * 256 + threadIdx.x;
    if (i >= n8) return;
    int f = (i & 15) * 8;
    union { uint4 u; __half2 h[4]; } in;
    in.u = X[i];
    union { uint4 u; __half2 h[4]; } o;
    #pragma unroll
    for (int q = 0; q < 4; ++q) {
        float2 v = __half22float2(in.h[q]);
        o.h[q] = __floats2half2_rn(
            silu_f(fmaf(v.x, mv[f + 2 * q + 0], mv[128 + f + 2 * q + 0])),
            silu_f(fmaf(v.y, mv[f + 2 * q + 1], mv[128 + f + 2 * q + 1])));
    }
    Y[i] = o.u;
}

// ---------------- fp16 mma.sync gather-GEMM, B direct from permuted gmem ----------------
// MODE: 0 = plain fp32 out, 1 = bias + FiLM fp16 out + per-CTA stats, 2 = bias+bias2 + idconv, fp16 out
template<int CIN, int MODE>
__global__ __launch_bounds__(256, 2)
void conv_mma_kernel(const __half* __restrict__ X, const int* __restrict__ nbr,
                     const uint4* __restrict__ PB, int chunk0,
                     const float* __restrict__ bias, const float* __restrict__ bias2,
                     const float* __restrict__ tp, const int* __restrict__ b_idx,
                     const __half* __restrict__ Xid, float* __restrict__ cpart,
                     void* __restrict__ outv, int M, int K) {
    extern __shared__ char sm[];
    const uint32_t smA = smem_u32(sm);            // A: 2 x 18432 B

    constexpr int CPK = CIN / 64;
    const int MAIN  = K * CPK;
    const int TOTAL = MAIN + ((MODE == 2) ? 1 : 0);

    const int t = threadIdx.x;
    const int lane = t & 31, w = t >> 5;
    const int warpM = w >> 2, warpN = w & 3;
    const int rowBase = blockIdx.x * TILE_M;

    const int lr = t >> 1;
    const int lh = t & 1;
    const int myRow = rowBase + lr;

    const int aRow = warpM * 64 + (lane & 15);
    const int aSeg = lane >> 4;

    float acc[4][4][4];
    #pragma unroll
    for (int i = 0; i < 4; ++i)
        #pragma unroll
        for (int j = 0; j < 4; ++j)
            #pragma unroll
            for (int q = 0; q < 4; ++q) acc[i][j][q] = 0.f;

    // A-side chunk decode
    struct AChunk { const __half* a; int aCIN; int cc; };
    auto decode = [&](int c) -> AChunk {
        AChunk ch;
        if (MODE != 2 || c < MAIN) {
            int k  = c / CPK;
            ch.cc = (c - k * CPK) * 64;
            ch.a = X; ch.aCIN = CIN;
        } else {
            ch.a = Xid; ch.aCIN = 64; ch.cc = 0;
        }
        return ch;
    };
    // neighbor index for chunk c
    auto ldIdx = [&](int c) -> int {
        if (c >= TOTAL || myRow >= M) return -1;
        if (MODE != 2 || c < MAIN) return nbr[(size_t)(c / CPK) * M + myRow];
        return myRow;   // idconv identity
    };

    uint4 va[4];
    auto gatherA = [&](const AChunk& ch, int idx) {
        if (idx >= 0) {
            const uint4* p = (const uint4*)(ch.a + (size_t)idx * ch.aCIN + ch.cc) + lh * 4;
            va[0] = p[0]; va[1] = p[1]; va[2] = p[2]; va[3] = p[3];
        } else {
            va[0] = va[1] = va[2] = va[3] = make_uint4(0, 0, 0, 0);
        }
    };
    auto stsA = [&](int bu) {
        char* dst = sm + bu * STAGE_BYTES + (lr * ROWU + lh * 4) * 16;
        #pragma unroll
        for (int j = 0; j < 4; ++j) ((uint4*)dst)[j] = va[j];
    };

    // B fragment prefetch: running pointer, stride 256 uint4 per k-step.
    // Unconditional issue (PB has 2 k-steps of overread padding); L1 evict_last.
    uint4 blo[2], bhi[2];
    const uint4* pb = PB + (size_t)chunk0 * 1024 + warpN * 64 + lane;
    #define ISSUE_B(p) do { blo[p] = ldg_el(pb); bhi[p] = ldg_el(pb + 32); pb += 256; } while (0)

    ISSUE_B(0);
    ISSUE_B(1);

    // prologue A: idx + gather for chunk 0; chunk 1 shares k when CPK==2
    int idxCur = ldIdx(0);
    {
        AChunk c0 = decode(0);
        int idx = idxCur;
        if (CPK == 1) idxCur = ldIdx(1);   // CPK==2: chunk 1 reuses chunk 0's idx
        gatherA(c0, idx);
    }

    for (int c = 0; c < TOTAL; ++c) {
        const int bu = c & 1;
        stsA(bu);
        // issue next chunk's gather BEFORE the barrier (idx already available)
        if (c + 1 < TOTAL) {
            AChunk cn = decode(c + 1);
            int idx = idxCur;
            // prefetch idx for chunk c+2; with CPK==2, chunks (2k,2k+1) share idx,
            // so only load when chunk c+2 starts a new k (c even)
            if (CPK == 1 || (c & 1) == 0) idxCur = ldIdx(c + 2);
            gatherA(cn, idx);
        }
        __syncthreads();

        const uint32_t abuf = smA + bu * STAGE_BYTES;
        #pragma unroll
        for (int kt = 0; kt < 4; ++kt) {
            const int p = kt & 1;
            uint4 lo = blo[p], hi = bhi[p];
            ISSUE_B(p);
            uint32_t a[4][4];
            #pragma unroll
            for (int mt = 0; mt < 4; ++mt)
                ldsm4(a[mt], abuf + ((aRow + mt * 16) * ROWU + 2 * kt + aSeg) * 16);
            #pragma unroll
            for (int mt = 0; mt < 4; ++mt) {
                mma_f16(acc[mt][0], a[mt], lo.x, lo.y);
                mma_f16(acc[mt][1], a[mt], lo.z, lo.w);
                mma_f16(acc[mt][2], a[mt], hi.x, hi.y);
                mma_f16(acc[mt][3], a[mt], hi.z, hi.w);
            }
        }
    }
    #undef ISSUE_B

    // ---- epilogue ----
    float ss[8], sq[8];
    if (MODE == 1) {
        #pragma unroll
        for (int q = 0; q < 8; ++q) { ss[q] = 0.f; sq[q] = 0.f; }
    }
    #pragma unroll
    for (int mt = 0; mt < 4; ++mt) {
        int row0 = rowBase + warpM * 64 + mt * 16 + (lane >> 2);
        #pragma unroll
        for (int hr = 0; hr < 2; ++hr) {
            int row = row0 + 8 * hr;
            if (row >= M) continue;
            const float* tpr = (MODE == 1) ? (tp + b_idx[row] * 256) : nullptr;
            #pragma unroll
            for (int nt = 0; nt < 4; ++nt) {
                int col = warpN * 32 + nt * 8 + 2 * (lane & 3);
                float v0 = acc[mt][nt][2 * hr + 0];
                float v1 = acc[mt][nt][2 * hr + 1];
                if (MODE == 1) {
                    v0 = (v0 + bias[col])     * (1.f + tpr[col])     + tpr[128 + col];
                    v1 = (v1 + bias[col + 1]) * (1.f + tpr[col + 1]) + tpr[129 + col];
                    ss[2 * nt]     += v0; sq[2 * nt]     += v0 * v0;
                    ss[2 * nt + 1] += v1; sq[2 * nt + 1] += v1 * v1;
                    __half* out = (__half*)outv;
                    *(__half2*)(out + (size_t)row * 128 + col) = __floats2half2_rn(v0, v1);
                } else if (MODE == 2) {
                    v0 += bias[col] + bias2[col];
                    v1 += bias[col + 1] + bias2[col + 1];
                    __half* out = (__half*)outv;
                    *(__half2*)(out + (size_t)row * 128 + col) = __floats2half2_rn(v0, v1);
                } else {
                    float* out = (float*)outv;
                    *(float2*)(out + (size_t)row * 128 + col) = make_float2(v0, v1);
                }
            }
        }
    }

    if (MODE == 1) {
        #pragma unroll
        for (int q = 0; q < 8; ++q) {
            #pragma unroll
            for (int off = 4; off <= 16; off <<= 1) {
                ss[q] += __shfl_xor_sync(0xffffffff, ss[q], off);
                sq[q] += __shfl_xor_sync(0xffffffff, sq[q], off);
            }
        }
        __syncthreads();
        float* sstat = (float*)sm;       // [2 warpM][256]
        if (lane < 4) {
            #pragma unroll
            for (int nt = 0; nt < 4; ++nt)
                #pragma unroll
                for (int p = 0; p < 2; ++p) {
                    int col = warpN * 32 + nt * 8 + 2 * lane + p;
                    sstat[warpM * 256 + col]       = ss[2 * nt + p];
                    sstat[warpM * 256 + 128 + col] = sq[2 * nt + p];
                }
        }
        __syncthreads();
        if (t < 256)
            cpart[(size_t)blockIdx.x * 256 + t] = sstat[t] + sstat[256 + t];
    }
}

// ---------------- launch ----------------
extern "C" void kernel_launch(void* const* d_in, const int* in_sizes, int n_in,
                              void* d_out, int out_size) {
    const float* x     = (const float*)d_in[0];
    const float* t     = (const float*)d_in[1];
    const int*   b_idx = (const int*)  d_in[2];
    const int*   nbr   = (const int*)  d_in[3];
    const int*   nbrd  = (const int*)  d_in[4];
    const float* g1    = (const float*)d_in[5];
    const float* be1   = (const float*)d_in[6];
    const float* W1    = (const float*)d_in[7];
    const float* b1    = (const float*)d_in[8];
    const float* Wt    = (const float*)d_in[9];
    const float* bt    = (const float*)d_in[10];
    const float* g2    = (const float*)d_in[11];
    const float* be2   = (const float*)d_in[12];
    const float* W2    = (const float*)d_in[13];
    const float* b2    = (const float*)d_in[14];
    const float* Wid   = (const float*)d_in[15];
    const float* bid   = (const float*)d_in[16];
    const float* Wd    = (const float*)d_in[17];
    float* out = (float*)d_out;

    __half *pa, *ph, *ph2, *pxr;
    float *ppart, *pcpart, *pmv, *ptp;
    uint2 *pPB;
    cudaGetSymbolAddress((void**)&pa,     g_a);
    cudaGetSymbolAddress((void**)&ph,     g_h);
    cudaGetSymbolAddress((void**)&ph2,    g_h2);
    cudaGetSymbolAddress((void**)&pxr,    g_xr);
    cudaGetSymbolAddress((void**)&ppart,  g_part);
    cudaGetSymbolAddress((void**)&pcpart, g_cpart);
    cudaGetSymbolAddress((void**)&pmv,    g_mv);
    cudaGetSymbolAddress((void**)&ptp,    g_tp);
    cudaGetSymbolAddress((void**)&pPB,    g_PB);

    cudaFuncSetAttribute(conv_mma_kernel<64, 1>,  cudaFuncAttributeMaxDynamicSharedMemorySize, CONV_SMEM);
    cudaFuncSetAttribute(conv_mma_kernel<128, 2>, cudaFuncAttributeMaxDynamicSharedMemorySize, CONV_SMEM);
    cudaFuncSetAttribute(conv_mma_kernel<128, 0>, cudaFuncAttributeMaxDynamicSharedMemorySize, CONV_SMEM);

    const float invn = 1.0f / (float)NN;

    // launch 0: fused prologue (stats1 + round x | B-frag prep | tproj)
    prologue_kernel<<<905, 256>>>(x, t, Wt, bt, W1, W2, Wid, Wd,
                                  ppart, ptp, pPB, pxr);
    // launch 1: BN1 finalize
    bn_finalize_kernel<NI><<<1, 512>>>(ppart, STATS_BLOCKS, invn, g1, be1, pmv);
    // launch 2: BN1 apply + SiLU -> a (fp16)
    {
        int n8 = NN * NI / 8;
        bn_apply_silu_kernel<NI><<<(n8 + 255) / 256, 256>>>((const float4*)x, pmv, (uint4*)pa, n8);
    }
    // launch 3 (ncu-profiled): conv1 (+bias +FiLM + stats) -> h (fp16)
    conv_mma_kernel<64, 1><<<NCTA, 256, CONV_SMEM>>>(
        pa, nbr, (const uint4*)pPB, 0, b1, nullptr, ptp, b_idx, nullptr, pcpart, ph, NN, KK);
    // launch 4: BN2 finalize from conv1 partials
    bn_finalize_cpart_kernel<<<1, 1024>>>(pcpart, invn, g2, be2, pmv);
    // launch 5: BN2 apply + SiLU (fp16 in) -> a (fp16)
    {
        int n8 = NN * NFD / 8;
        bn_apply_silu_h16_kernel<<<(n8 + 255) / 256, 256>>>((const uint4*)ph, pmv, (uint4*)pa, n8);
    }
    // launch 6: conv2 + fused idconv (+b2+bid) -> h2 (fp16)
    conv_mma_kernel<128, 2><<<NCTA, 256, CONV_SMEM>>>(
        pa, nbr, (const uint4*)pPB, 27, b2, bid, nullptr, nullptr, pxr, nullptr, ph2, NN, KK);
    // launch 7: strided down conv -> out (fp32)
    conv_mma_kernel<128, 0><<<DOWNCTA, 256, CONV_SMEM>>>(
        ph2, nbrd, (const uint4*)pPB, 82, nullptr, nullptr, nullptr, nullptr, nullptr, nullptr,
        out, NDD, KDD);

    (void)in_sizes; (void)n_in; (void)out_size;
}